// round 2
// baseline (speedup 1.0000x reference)
#include <cuda_runtime.h>
#include <cuda_bf16.h>
#include <math.h>
#include <float.h>

// ---------------- problem constants ----------------
#define BATCH 8
#define CIN 512
#define HF 60
#define SP (HF*HF)          // 3600
#define NCLS 19
#define HI 480
#define PATCH 10
#define NPI 2304            // (480/10)^2
#define NPF 36              // (60/10)^2
#define XSIZE ((long)BATCH*NCLS*HI*HI)   // 35,020,800

// ---------------- scratch (device globals; no allocation allowed) ----------------
__device__ float g_pooled[BATCH*CIN*50];       // [b][c][50]  (p1|p2:4|p3:9|p6:36)
__device__ float g_z[BATCH*CIN*50];            // w_conv-projected branches, same layout
__device__ float g_bsum[BATCH*CIN*SP];         // sum of upsampled projected branches
__device__ float g_x512[BATCH*CIN*SP];         // conv+bn+relu output
__device__ float g_segp[4*BATCH*NCLS*SP];      // segconv partials (4 channel groups)
__device__ float g_x60[BATCH*NCLS*SP];         // seg logits at 60x60
__device__ float g_unf[BATCH*NCLS*NPF*100];    // unfolded argmax pool [b][c][36][100]

// ---------------- kernel 1: hierarchical adaptive pools ----------------
__global__ void pool_kernel(const float* __restrict__ feat) {
    int plane = blockIdx.x;                 // b*512+c
    const float* src = feat + (size_t)plane * SP;
    __shared__ float part[360];
    __shared__ float p6[36];
    int t = threadIdx.x;                    // 360 threads
    int cell = t / 10, r = t % 10;
    int cy = cell / 6, cx = cell % 6;
    const float* rp = src + (cy*10 + r)*60 + cx*10;
    float s = 0.f;
    #pragma unroll
    for (int i = 0; i < 10; i++) s += rp[i];
    part[t] = s;
    __syncthreads();
    if (t < 36) {
        float s2 = 0.f;
        #pragma unroll
        for (int i = 0; i < 10; i++) s2 += part[t*10 + i];
        p6[t] = s2 * 0.01f;
    }
    __syncthreads();
    float* dst = g_pooled + (size_t)plane * 50;
    if (t == 0) {
        float s3 = 0.f;
        for (int i = 0; i < 36; i++) s3 += p6[i];
        dst[0] = s3 * (1.f/36.f);
    } else if (t < 5) {               // p=2 : 2x2 grid, each = mean of 3x3 p6 cells
        int i = (t-1)/2, j = (t-1)%2;
        float s3 = 0.f;
        for (int dy = 0; dy < 3; dy++)
            for (int dx = 0; dx < 3; dx++) s3 += p6[(i*3+dy)*6 + j*3+dx];
        dst[t] = s3 * (1.f/9.f);
    } else if (t < 14) {              // p=3 : 3x3 grid, each = mean of 2x2 p6 cells
        int i = (t-5)/3, j = (t-5)%3;
        float s3 = 0.f;
        for (int dy = 0; dy < 2; dy++)
            for (int dx = 0; dx < 2; dx++) s3 += p6[(i*2+dy)*6 + j*2+dx];
        dst[t] = s3 * 0.25f;
    } else if (t < 50) {
        dst[t] = p6[t-14];
    }
}

// ---------------- kernel 2: tiny PSP convs + project through w_conv ----------------
__global__ void psp_kernel(const float* __restrict__ w_psp, const float* __restrict__ b_psp0,
                           const float* __restrict__ bng, const float* __restrict__ bnb,
                           const float* __restrict__ bnm, const float* __restrict__ bnv,
                           const float* __restrict__ w_conv) {
    int blk = blockIdx.x;           // b*50 + s
    int b = blk / 50, s = blk % 50;
    int br;
    if (s == 0) br = 0; else if (s < 5) br = 1; else if (s < 14) br = 2; else br = 3;
    __shared__ float vin[512];
    __shared__ float mid[128];
    int t = threadIdx.x;            // 512
    vin[t] = g_pooled[(size_t)(b*512 + t)*50 + s];
    __syncthreads();
    if (t < 128) {
        const float* wr = w_psp + ((size_t)br*128 + t)*512;
        float acc = 0.f;
        #pragma unroll 8
        for (int c = 0; c < 512; c++) acc += wr[c] * vin[c];
        if (br == 0) acc += b_psp0[t];
        else {
            int ii = br - 1;
            float sc = bng[ii*128+t] / sqrtf(bnv[ii*128+t] + 1e-5f);
            acc = (acc - bnm[ii*128+t]) * sc + bnb[ii*128+t];
        }
        mid[t] = fmaxf(acc, 0.f);
    }
    __syncthreads();
    const float* wr = w_conv + (size_t)t*1024 + br*128;
    float acc = 0.f;
    #pragma unroll 8
    for (int c = 0; c < 128; c++) acc += wr[c] * mid[c];
    g_z[((size_t)b*512 + t)*50 + s] = acc;
}

// ---------------- kernel 3: upsample projected branches, sum ----------------
__device__ __forceinline__ float interp_p(const float* z, int p, int h, int w) {
    float sc = (float)(p-1) / 59.f;
    float sy = h * sc, sx = w * sc;
    int y0 = (int)sy, x0 = (int)sx;
    int y1 = min(y0+1, p-1), x1 = min(x0+1, p-1);
    float wy = sy - (float)y0, wx = sx - (float)x0;
    float tp = (1.f-wx)*z[y0*p+x0] + wx*z[y0*p+x1];
    float bo = (1.f-wx)*z[y1*p+x0] + wx*z[y1*p+x1];
    return (1.f-wy)*tp + wy*bo;
}

__global__ void bsum_kernel() {
    int plane = blockIdx.y;                      // b*512+o
    int hw = blockIdx.x * 240 + threadIdx.x;
    int h = hw / 60, w = hw % 60;
    const float* zb = g_z + (size_t)plane * 50;
    float v = zb[0];
    v += interp_p(zb + 1, 2, h, w);
    v += interp_p(zb + 5, 3, h, w);
    v += interp_p(zb + 14, 6, h, w);
    g_bsum[(size_t)plane*SP + hw] = v;
}

// ---------------- kernel 4: main GEMM (feat half of w_conv) + BN + relu ----------------
// C[o,n] = sum_c Wf[o,c]*feat[b,c,n];  x512 = relu(bn(C + bsum))
__global__ __launch_bounds__(256) void gemm_kernel(const float* __restrict__ w_conv,
                                                   const float* __restrict__ feat,
                                                   const float* __restrict__ cg,
                                                   const float* __restrict__ cb,
                                                   const float* __restrict__ cm,
                                                   const float* __restrict__ cv) {
    const int b = blockIdx.z;
    const int mBase = blockIdx.y * 128;
    const int nBase = blockIdx.x * 128;
    const int tid = threadIdx.x;
    __shared__ float As[16*132];
    __shared__ float Bs[16*132];
    const int tm = (tid / 16) * 8;
    const int tn = (tid % 16) * 8;
    float acc[8][8];
    #pragma unroll
    for (int i = 0; i < 8; i++)
        #pragma unroll
        for (int j = 0; j < 8; j++) acc[i][j] = 0.f;

    const float* Bbase = feat + (size_t)b * 512 * SP;
    float4 aReg[2], bReg[2];

    auto loadA = [&](int k0) {
        #pragma unroll
        for (int s = 0; s < 2; s++) {
            int f = tid + s*256;
            int o = f >> 2, c4 = (f & 3) * 4;
            aReg[s] = *(const float4*)(w_conv + (size_t)(mBase+o)*1024 + 512 + k0 + c4);
        }
    };
    auto loadB = [&](int k0) {
        #pragma unroll
        for (int s = 0; s < 2; s++) {
            int f = tid + s*256;
            int c = f >> 5, n4 = (f & 31) * 4;
            int col = nBase + n4;
            if (col < SP) bReg[s] = *(const float4*)(Bbase + (size_t)(k0+c)*SP + col);
            else          bReg[s] = make_float4(0.f,0.f,0.f,0.f);
        }
    };
    auto storeAB = [&]() {
        #pragma unroll
        for (int s = 0; s < 2; s++) {
            int f = tid + s*256;
            int o = f >> 2, c4 = (f & 3) * 4;
            As[(c4+0)*132+o] = aReg[s].x; As[(c4+1)*132+o] = aReg[s].y;
            As[(c4+2)*132+o] = aReg[s].z; As[(c4+3)*132+o] = aReg[s].w;
            int c = f >> 5, n4 = (f & 31) * 4;
            *(float4*)&Bs[c*132+n4] = bReg[s];
        }
    };

    loadA(0); loadB(0);
    storeAB();
    __syncthreads();
    for (int kt = 0; kt < 32; kt++) {
        if (kt < 31) { loadA((kt+1)*16); loadB((kt+1)*16); }
        #pragma unroll
        for (int kk = 0; kk < 16; kk++) {
            float4 a0 = *(float4*)&As[kk*132+tm];
            float4 a1 = *(float4*)&As[kk*132+tm+4];
            float4 b0 = *(float4*)&Bs[kk*132+tn];
            float4 b1 = *(float4*)&Bs[kk*132+tn+4];
            float av[8] = {a0.x,a0.y,a0.z,a0.w,a1.x,a1.y,a1.z,a1.w};
            float bv[8] = {b0.x,b0.y,b0.z,b0.w,b1.x,b1.y,b1.z,b1.w};
            #pragma unroll
            for (int i = 0; i < 8; i++)
                #pragma unroll
                for (int j = 0; j < 8; j++) acc[i][j] += av[i]*bv[j];
        }
        __syncthreads();
        if (kt < 31) { storeAB(); __syncthreads(); }
    }
    #pragma unroll
    for (int i = 0; i < 8; i++) {
        int o = mBase + tm + i;
        float sc = cg[o] / sqrtf(cv[o] + 1e-5f);
        float mn = cm[o], bt = cb[o];
        const float* bs = g_bsum + (size_t)(b*512+o)*SP;
        float* xo = g_x512 + (size_t)(b*512+o)*SP;
        #pragma unroll
        for (int j = 0; j < 8; j++) {
            int n = nBase + tn + j;
            if (n < SP) {
                float v = acc[i][j] + bs[n];
                xo[n] = fmaxf((v - mn)*sc + bt, 0.f);
            }
        }
    }
}

// ---------------- kernel 5: 3x3 segconv (channel-split partials) ----------------
__global__ __launch_bounds__(180) void segconv_kernel(const float* __restrict__ wseg) {
    int rt = blockIdx.x, cgrp = blockIdx.y, b = blockIdx.z;
    int tid = threadIdx.x;               // 180
    int ty = tid / 30, lx = tid % 30;
    int w0 = lx * 2;
    __shared__ float sIn[8*8*64];
    __shared__ float sW[8*9*19];
    float a0[NCLS], a1[NCLS];
    #pragma unroll
    for (int o = 0; o < NCLS; o++) { a0[o] = 0.f; a1[o] = 0.f; }
    int row0 = rt * 6;
    const float* xin = g_x512 + (size_t)b * 512 * SP;
    for (int ccB = 0; ccB < 16; ccB++) {
        int c0 = cgrp*128 + ccB*8;
        for (int e = tid; e < 8*8*62; e += 180) {
            int ch = e / 496; int rem = e % 496; int r = rem / 62; int j = rem % 62;
            int gr = row0 - 1 + r, gc = j - 1;
            float v = 0.f;
            if (gr >= 0 && gr < 60 && gc >= 0 && gc < 60)
                v = xin[(size_t)(c0+ch)*SP + gr*60 + gc];
            sIn[ch*512 + r*64 + j] = v;
        }
        for (int e = tid; e < 1368; e += 180) {
            int o = e / 72; int rem = e % 72; int ch = rem / 9; int kk = rem % 9;
            sW[ch*171 + kk*19 + o] = wseg[((size_t)o*512 + c0+ch)*9 + kk];
        }
        __syncthreads();
        #pragma unroll 2
        for (int ch = 0; ch < 8; ch++) {
            #pragma unroll
            for (int ky = 0; ky < 3; ky++) {
                int base = ch*512 + (ty+ky)*64 + w0;
                float r0 = sIn[base], r1 = sIn[base+1], r2 = sIn[base+2], r3 = sIn[base+3];
                const float* wb = &sW[ch*171 + ky*57];
                #pragma unroll
                for (int o = 0; o < NCLS; o++) {
                    float w0v = wb[o], w1v = wb[19+o], w2v = wb[38+o];
                    a0[o] += r0*w0v + r1*w1v + r2*w2v;
                    a1[o] += r1*w0v + r2*w1v + r3*w2v;
                }
            }
        }
        __syncthreads();
    }
    int h = row0 + ty;
    float* pp = g_segp + (size_t)((cgrp*8 + b)*NCLS) * SP;
    #pragma unroll
    for (int o = 0; o < NCLS; o++) {
        pp[(size_t)o*SP + h*60 + w0]   = a0[o];
        pp[(size_t)o*SP + h*60 + w0+1] = a1[o];
    }
}

__global__ void segreduce_kernel(const float* __restrict__ bias) {
    int i = blockIdx.x*256 + threadIdx.x;
    if (i >= BATCH*NCLS*SP) return;
    int o = (i / SP) % NCLS;
    int b = i / (NCLS*SP);
    int hw = i % SP;
    float s = bias[o];
    #pragma unroll
    for (int c = 0; c < 4; c++) s += g_segp[(size_t)((c*8+b)*NCLS + o)*SP + hw];
    g_x60[i] = s;
}

// ---------------- kernel 6: per-pixel argmax of bilinear(x60) -> unfolded pool ----------------
__global__ void unfold_kernel() {
    int fx = blockIdx.x, fy = blockIdx.y, b = blockIdx.z;
    int t = threadIdx.x;                   // 64
    int dy = t / 8, dx = t % 8;
    int Y = fy*8 + dy, X = fx*8 + dx;
    const float r = 59.f / 479.f;
    float sy = Y * r, sx = X * r;
    int y0 = (int)sy, x0 = (int)sx;
    int y1 = min(y0+1, 59), x1 = min(x0+1, 59);
    float wy = sy - (float)y0, wx = sx - (float)x0;
    const float* xb = g_x60 + (size_t)b * NCLS * SP;
    int i00 = y0*60+x0, i01 = y0*60+x1, i10 = y1*60+x0, i11 = y1*60+x1;
    float bv = -FLT_MAX; int bi = 0;
    for (int c = 0; c < NCLS; c++) {
        const float* p = xb + (size_t)c*SP;
        float t0 = (1.f-wx)*p[i00] + wx*p[i01];
        float t1 = (1.f-wx)*p[i10] + wx*p[i11];
        float v = (1.f-wy)*t0 + wy*t1;
        if (v > bv) { bv = v; bi = c; }
    }
    __shared__ int cnt[NCLS];
    if (t < NCLS) cnt[t] = 0;
    __syncthreads();
    atomicAdd(&cnt[bi], 1);
    __syncthreads();
    if (t < NCLS) {
        int k = (fy/10)*6 + fx/10;
        int q = (fy%10)*10 + fx%10;
        g_unf[((size_t)(b*NCLS + t)*NPF + k)*100 + q] = (float)cnt[t] * (1.f/64.f);
    }
}

// ---------------- kernel 7: fused attn-matmul + fold + upsample + x*(1+corr) ----------------
__global__ __launch_bounds__(400) void final_kernel(const float* __restrict__ att,
                                                    float* __restrict__ out) {
    int b = blockIdx.z, c = blockIdx.y;
    int pbase = blockIdx.x * 64;
    int tx = threadIdx.x, ty = threadIdx.y;     // (25,16)
    int tid = ty*25 + tx;
    __shared__ __align__(16) float attT[36*65];
    __shared__ __align__(16) float unfS[3600];
    __shared__ float inv[64];
    const float* ab = att + ((size_t)(b*NCLS + c)*NPI + pbase) * 36;
    for (int e = tid; e < 64*36; e += 400) {
        int p = e / 36, k = e % 36;
        attT[k*65 + p] = ab[e];
    }
    const float* ub = g_unf + (size_t)(b*NCLS + c) * 3600;
    for (int e = tid; e < 3600; e += 400) unfS[e] = ub[e];
    __syncthreads();
    if (tid < 64) {
        int cn = 0;
        #pragma unroll 4
        for (int k = 0; k < 36; k++) cn += (attT[k*65 + tid] != 0.f);
        inv[tid] = 1.f / ((float)cn + 1e-5f);
    }
    __syncthreads();
    float acc[4][4];
    #pragma unroll
    for (int i = 0; i < 4; i++)
        #pragma unroll
        for (int j = 0; j < 4; j++) acc[i][j] = 0.f;
    int q0 = tx * 4;
    int p0 = ty * 4;
    #pragma unroll 4
    for (int k = 0; k < 36; k++) {
        float4 u = *(float4*)&unfS[k*100 + q0];
        float av0 = attT[k*65 + p0 + 0];
        float av1 = attT[k*65 + p0 + 1];
        float av2 = attT[k*65 + p0 + 2];
        float av3 = attT[k*65 + p0 + 3];
        acc[0][0] += av0*u.x; acc[0][1] += av0*u.y; acc[0][2] += av0*u.z; acc[0][3] += av0*u.w;
        acc[1][0] += av1*u.x; acc[1][1] += av1*u.y; acc[1][2] += av1*u.z; acc[1][3] += av1*u.w;
        acc[2][0] += av2*u.x; acc[2][1] += av2*u.y; acc[2][2] += av2*u.z; acc[2][3] += av2*u.w;
        acc[3][0] += av3*u.x; acc[3][1] += av3*u.y; acc[3][2] += av3*u.z; acc[3][3] += av3*u.w;
    }
    const float* xb = g_x60 + (size_t)(b*NCLS + c) * SP;
    float* ob = out + (size_t)(b*NCLS + c) * (HI*HI);
    const float r = 59.f / 479.f;
    #pragma unroll
    for (int i = 0; i < 4; i++) {
        int p = pbase + p0 + i;
        int Py = p / 48, Px = p % 48;
        float ci = inv[p0 + i];
        #pragma unroll
        for (int j = 0; j < 4; j++) {
            int q = q0 + j;
            int y = Py*10 + q/10;
            int x = Px*10 + q%10;
            float sy = y * r, sx = x * r;
            int y0 = (int)sy, x0 = (int)sx;
            int y1 = min(y0+1, 59), x1 = min(x0+1, 59);
            float wy = sy - (float)y0, wx = sx - (float)x0;
            float t0 = (1.f-wx)*xb[y0*60+x0] + wx*xb[y0*60+x1];
            float t1 = (1.f-wx)*xb[y1*60+x0] + wx*xb[y1*60+x1];
            float xv = (1.f-wy)*t0 + wy*t1;
            float corr = acc[i][j] * ci;
            ob[y*HI + x] = corr*xv + xv;
        }
    }
}

// ---------------- launcher ----------------
extern "C" void kernel_launch(void* const* d_in, const int* in_sizes, int n_in,
                              void* d_out, int out_size) {
    const float* feat   = (const float*)d_in[0];
    const float* att    = (const float*)d_in[1];
    const float* w_psp  = (const float*)d_in[2];
    const float* b_psp0 = (const float*)d_in[3];
    const float* bng    = (const float*)d_in[4];
    const float* bnb    = (const float*)d_in[5];
    const float* bnm    = (const float*)d_in[6];
    const float* bnv    = (const float*)d_in[7];
    const float* w_conv = (const float*)d_in[8];
    const float* cgam   = (const float*)d_in[9];
    const float* cbet   = (const float*)d_in[10];
    const float* cmea   = (const float*)d_in[11];
    const float* cvar   = (const float*)d_in[12];
    const float* wseg   = (const float*)d_in[13];
    const float* bseg   = (const float*)d_in[14];
    float* out = (float*)d_out;
    cudaStream_t st = 0;

    pool_kernel<<<BATCH*CIN, 360, 0, st>>>(feat);
    psp_kernel<<<BATCH*50, 512, 0, st>>>(w_psp, b_psp0, bng, bnb, bnm, bnv, w_conv);
    bsum_kernel<<<dim3(15, BATCH*CIN), 240, 0, st>>>();
    gemm_kernel<<<dim3(29, 4, BATCH), 256, 0, st>>>(w_conv, feat, cgam, cbet, cmea, cvar);
    segconv_kernel<<<dim3(10, 4, BATCH), 180, 0, st>>>(wseg);
    segreduce_kernel<<<(BATCH*NCLS*SP + 255)/256, 256, 0, st>>>(bseg);
    unfold_kernel<<<dim3(60, 60, BATCH), 64, 0, st>>>();
    final_kernel<<<dim3(36, NCLS, BATCH), dim3(25, 16), 0, st>>>(att, out);

    long attsz = (long)in_sizes[1];
    if ((long)out_size >= XSIZE + attsz) {
        cudaMemcpyAsync(out + XSIZE, att, (size_t)attsz * sizeof(float),
                        cudaMemcpyDeviceToDevice, st);
    }
}

// round 6
// speedup vs baseline: 1.0115x; 1.0115x over previous
#include <cuda_runtime.h>
#include <cuda_bf16.h>
#include <math.h>
#include <float.h>
#include <stdint.h>

// ---------------- problem constants ----------------
#define BATCH 8
#define CIN 512
#define HF 60
#define SP (HF*HF)          // 3600
#define NCLS 19
#define HI 480
#define PATCH 10
#define NPI 2304            // (480/10)^2
#define NPF 36              // (60/10)^2
#define XSIZE ((long)BATCH*NCLS*HI*HI)   // 35,020,800

// ---------------- scratch (device globals; no allocation allowed) ----------------
__device__ float g_pooled[BATCH*CIN*50];       // [b][c][50]  (p1|p2:4|p3:9|p6:36)
__device__ float g_z[BATCH*CIN*50];            // w_conv-projected branches, same layout
__device__ float g_bsum[BATCH*CIN*SP];         // sum of upsampled projected branches
__device__ float g_x512[BATCH*CIN*SP];         // conv+bn+relu output
__device__ float g_segp[4*BATCH*NCLS*SP];      // segconv partials (4 channel groups)
__device__ float g_x60[BATCH*NCLS*SP];         // seg logits at 60x60
__device__ float g_unf[BATCH*NCLS*NPF*100];    // unfolded argmax pool [b][c][36][100]

// ---------------- helpers ----------------
__device__ __forceinline__ uint32_t smem_to_u32(const void* smem_ptr) {
    uint32_t addr;
    asm("{ .reg .u64 tmp; cvta.to.shared.u64 tmp, %1; cvt.u32.u64 %0, tmp; }"
        : "=r"(addr) : "l"(smem_ptr));
    return addr;
}
#define SMEM_SWIZZLE_128B(byte_offset) \
    ((byte_offset) ^ (((byte_offset) >> 3) & 0x70))

__device__ __forceinline__ void ldsm_x4(uint32_t& r0, uint32_t& r1, uint32_t& r2, uint32_t& r3,
                                        uint32_t addr) {
    asm volatile("ldmatrix.sync.aligned.m8n8.x4.shared.b16 {%0,%1,%2,%3}, [%4];"
                 : "=r"(r0), "=r"(r1), "=r"(r2), "=r"(r3) : "r"(addr));
}
__device__ __forceinline__ void mma16816(float* c, const uint32_t* a, uint32_t b0, uint32_t b1) {
    asm volatile(
        "mma.sync.aligned.m16n8k16.row.col.f32.bf16.bf16.f32 "
        "{%0,%1,%2,%3}, {%4,%5,%6,%7}, {%8,%9}, {%0,%1,%2,%3};"
        : "+f"(c[0]), "+f"(c[1]), "+f"(c[2]), "+f"(c[3])
        : "r"(a[0]), "r"(a[1]), "r"(a[2]), "r"(a[3]), "r"(b0), "r"(b1));
}
__device__ __forceinline__ uint32_t pk_bf16(__nv_bfloat16 a, __nv_bfloat16 b) {
    return (uint32_t)__bfloat16_as_ushort(a) | ((uint32_t)__bfloat16_as_ushort(b) << 16);
}

// ---------------- kernel 1: hierarchical adaptive pools ----------------
__global__ void pool_kernel(const float* __restrict__ feat) {
    int plane = blockIdx.x;                 // b*512+c
    const float* src = feat + (size_t)plane * SP;
    __shared__ float part[360];
    __shared__ float p6[36];
    int t = threadIdx.x;                    // 360 threads
    int cell = t / 10, r = t % 10;
    int cy = cell / 6, cx = cell % 6;
    const float* rp = src + (cy*10 + r)*60 + cx*10;
    float s = 0.f;
    #pragma unroll
    for (int i = 0; i < 10; i++) s += rp[i];
    part[t] = s;
    __syncthreads();
    if (t < 36) {
        float s2 = 0.f;
        #pragma unroll
        for (int i = 0; i < 10; i++) s2 += part[t*10 + i];
        p6[t] = s2 * 0.01f;
    }
    __syncthreads();
    float* dst = g_pooled + (size_t)plane * 50;
    if (t == 0) {
        float s3 = 0.f;
        for (int i = 0; i < 36; i++) s3 += p6[i];
        dst[0] = s3 * (1.f/36.f);
    } else if (t < 5) {
        int i = (t-1)/2, j = (t-1)%2;
        float s3 = 0.f;
        for (int dy = 0; dy < 3; dy++)
            for (int dx = 0; dx < 3; dx++) s3 += p6[(i*3+dy)*6 + j*3+dx];
        dst[t] = s3 * (1.f/9.f);
    } else if (t < 14) {
        int i = (t-5)/3, j = (t-5)%3;
        float s3 = 0.f;
        for (int dy = 0; dy < 2; dy++)
            for (int dx = 0; dx < 2; dx++) s3 += p6[(i*2+dy)*6 + j*2+dx];
        dst[t] = s3 * 0.25f;
    } else if (t < 50) {
        dst[t] = p6[t-14];
    }
}

// ---------------- kernel 2: tiny PSP convs + project through w_conv ----------------
__global__ void psp_kernel(const float* __restrict__ w_psp, const float* __restrict__ b_psp0,
                           const float* __restrict__ bng, const float* __restrict__ bnb,
                           const float* __restrict__ bnm, const float* __restrict__ bnv,
                           const float* __restrict__ w_conv) {
    int blk = blockIdx.x;           // b*50 + s
    int b = blk / 50, s = blk % 50;
    int br;
    if (s == 0) br = 0; else if (s < 5) br = 1; else if (s < 14) br = 2; else br = 3;
    __shared__ float vin[512];
    __shared__ float mid[128];
    int t = threadIdx.x;            // 512
    vin[t] = g_pooled[(size_t)(b*512 + t)*50 + s];
    __syncthreads();
    if (t < 128) {
        const float* wr = w_psp + ((size_t)br*128 + t)*512;
        float acc = 0.f;
        #pragma unroll 8
        for (int c = 0; c < 512; c++) acc += wr[c] * vin[c];
        if (br == 0) acc += b_psp0[t];
        else {
            int ii = br - 1;
            float sc = bng[ii*128+t] / sqrtf(bnv[ii*128+t] + 1e-5f);
            acc = (acc - bnm[ii*128+t]) * sc + bnb[ii*128+t];
        }
        mid[t] = fmaxf(acc, 0.f);
    }
    __syncthreads();
    const float* wr = w_conv + (size_t)t*1024 + br*128;
    float acc = 0.f;
    #pragma unroll 8
    for (int c = 0; c < 128; c++) acc += wr[c] * mid[c];
    g_z[((size_t)b*512 + t)*50 + s] = acc;
}

// ---------------- kernel 3: upsample projected branches, sum ----------------
__device__ __forceinline__ float interp_p(const float* z, int p, int h, int w) {
    float sc = (float)(p-1) / 59.f;
    float sy = h * sc, sx = w * sc;
    int y0 = (int)sy, x0 = (int)sx;
    int y1 = min(y0+1, p-1), x1 = min(x0+1, p-1);
    float wy = sy - (float)y0, wx = sx - (float)x0;
    float tp = (1.f-wx)*z[y0*p+x0] + wx*z[y0*p+x1];
    float bo = (1.f-wx)*z[y1*p+x0] + wx*z[y1*p+x1];
    return (1.f-wy)*tp + wy*bo;
}

__global__ void bsum_kernel() {
    int plane = blockIdx.y;                      // b*512+o
    int hw = blockIdx.x * 240 + threadIdx.x;
    int h = hw / 60, w = hw % 60;
    const float* zb = g_z + (size_t)plane * 50;
    float v = zb[0];
    v += interp_p(zb + 1, 2, h, w);
    v += interp_p(zb + 5, 3, h, w);
    v += interp_p(zb + 14, 6, h, w);
    g_bsum[(size_t)plane*SP + hw] = v;
}

// ---------------- kernel 4: HMMA bf16-split GEMM + BN + relu ----------------
// C[o,n] = sum_c Wf[o,c]*feat[b,c,n];  x512 = relu(bn(C + bsum))
// M=128, N=128, K=512 in 8 chunks of 64 (bf16).
// Split precision: x = hi + lo; D = Ahi*Bhi + Ahi*Blo + Alo*Bhi via mma.sync m16n8k16.
#define G_AHI 0
#define G_ALO 16384
#define G_BHI 32768
#define G_BLO 49152
#define G_SMEM_TOTAL 65536

__global__ __launch_bounds__(256) void gemm_mma_kernel(const float* __restrict__ w_conv,
                                                       const float* __restrict__ feat,
                                                       const float* __restrict__ cg,
                                                       const float* __restrict__ cb,
                                                       const float* __restrict__ cm,
                                                       const float* __restrict__ cv) {
    extern __shared__ char sm[];
    const int b = blockIdx.z;
    const int mBase = blockIdx.y * 128;
    const int nBase = blockIdx.x * 128;
    const int tid = threadIdx.x;
    const int wid = tid >> 5;
    const int lane = tid & 31;
    const int warp_m = (wid & 1) * 64;       // 2 warps over M
    const int warp_n = (wid >> 1) * 32;      // 4 warps over N
    const int g = lane >> 2, tig = lane & 3;
    uint32_t smb = smem_to_u32(sm);

    // ldmatrix lane-address components (matrix = lane>>3)
    const int a_row0 = warp_m + (((lane >> 3) & 1) << 3) + (lane & 7);
    const int a_kb   = ((lane >> 4) & 1) << 4;     // bytes
    const int b_row0 = warp_n + (((lane >> 4) & 1) << 3) + (lane & 7);
    const int b_kb   = ((lane >> 3) & 1) << 4;     // bytes

    float acc[4][4][4];
    #pragma unroll
    for (int i = 0; i < 4; i++)
        #pragma unroll
        for (int j = 0; j < 4; j++)
            #pragma unroll
            for (int k = 0; k < 4; k++) acc[i][j][k] = 0.f;

    const float* Bbase = feat + (size_t)b * 512 * SP;

    for (int c = 0; c < 8; c++) {
        int k0 = c * 64;
        // ---- A: 128 rows x 64 k fp32 -> hi/lo bf16, [m][k] SW128 rows of 128B
        #pragma unroll
        for (int e = tid; e < 2048; e += 256) {
            int o = e >> 4, j = e & 15;
            float4 v = *(const float4*)(w_conv + (size_t)(mBase + o)*1024 + 512 + k0 + j*4);
            __nv_bfloat16 h0 = __float2bfloat16(v.x), h1 = __float2bfloat16(v.y);
            __nv_bfloat16 h2 = __float2bfloat16(v.z), h3 = __float2bfloat16(v.w);
            __nv_bfloat16 l0 = __float2bfloat16(v.x - __bfloat162float(h0));
            __nv_bfloat16 l1 = __float2bfloat16(v.y - __bfloat162float(h1));
            __nv_bfloat16 l2 = __float2bfloat16(v.z - __bfloat162float(h2));
            __nv_bfloat16 l3 = __float2bfloat16(v.w - __bfloat162float(h3));
            uint32_t sw = SMEM_SWIZZLE_128B((uint32_t)(o*128 + j*8));
            *(uint2*)(sm + G_AHI + sw) = make_uint2(pk_bf16(h0,h1), pk_bf16(h2,h3));
            *(uint2*)(sm + G_ALO + sw) = make_uint2(pk_bf16(l0,l1), pk_bf16(l2,l3));
        }
        // ---- B: 64 k-rows x 128 n fp32 -> transposed [n][k] hi/lo bf16
        #pragma unroll
        for (int e = tid; e < 2048; e += 256) {
            int k = e >> 5, j = e & 31;
            int gcol = nBase + j*4;
            float4 v;
            if (gcol < SP) v = *(const float4*)(Bbase + (size_t)(k0 + k)*SP + gcol);
            else           v = make_float4(0.f, 0.f, 0.f, 0.f);
            float vv[4] = {v.x, v.y, v.z, v.w};
            #pragma unroll
            for (int e2 = 0; e2 < 4; e2++) {
                int n = j*4 + e2;
                __nv_bfloat16 h = __float2bfloat16(vv[e2]);
                __nv_bfloat16 l = __float2bfloat16(vv[e2] - __bfloat162float(h));
                uint32_t sw = SMEM_SWIZZLE_128B((uint32_t)(n*128 + k*2));
                *(unsigned short*)(sm + G_BHI + sw) = __bfloat16_as_ushort(h);
                *(unsigned short*)(sm + G_BLO + sw) = __bfloat16_as_ushort(l);
            }
        }
        __syncthreads();

        #pragma unroll
        for (int ks = 0; ks < 4; ks++) {
            int kByte = ks * 32;
            uint32_t ah[4][4], al[4][4], bh[2][4], bl[2][4];
            #pragma unroll
            for (int mt = 0; mt < 4; mt++) {
                uint32_t off = SMEM_SWIZZLE_128B((uint32_t)((a_row0 + mt*16)*128 + kByte + a_kb));
                ldsm_x4(ah[mt][0], ah[mt][1], ah[mt][2], ah[mt][3], smb + G_AHI + off);
                ldsm_x4(al[mt][0], al[mt][1], al[mt][2], al[mt][3], smb + G_ALO + off);
            }
            #pragma unroll
            for (int nt2 = 0; nt2 < 2; nt2++) {
                uint32_t off = SMEM_SWIZZLE_128B((uint32_t)((b_row0 + nt2*16)*128 + kByte + b_kb));
                ldsm_x4(bh[nt2][0], bh[nt2][1], bh[nt2][2], bh[nt2][3], smb + G_BHI + off);
                ldsm_x4(bl[nt2][0], bl[nt2][1], bl[nt2][2], bl[nt2][3], smb + G_BLO + off);
            }
            #pragma unroll
            for (int mt = 0; mt < 4; mt++) {
                #pragma unroll
                for (int nt = 0; nt < 4; nt++) {
                    int n2 = nt >> 1, p = nt & 1;
                    mma16816(acc[mt][nt], ah[mt], bh[n2][p*2], bh[n2][p*2+1]);
                    mma16816(acc[mt][nt], ah[mt], bl[n2][p*2], bl[n2][p*2+1]);
                    mma16816(acc[mt][nt], al[mt], bh[n2][p*2], bh[n2][p*2+1]);
                }
            }
        }
        __syncthreads();
    }

    // ---- epilogue: BN + relu + bsum, straight from accumulators ----
    #pragma unroll
    for (int mt = 0; mt < 4; mt++) {
        int mrow = mBase + warp_m + mt*16 + g;
        #pragma unroll
        for (int half = 0; half < 2; half++) {
            int o = mrow + half*8;
            float sc = cg[o] / sqrtf(cv[o] + 1e-5f);
            float mn = cm[o], bt = cb[o];
            const float* bs = g_bsum + (size_t)(b*512 + o)*SP;
            float* xo = g_x512 + (size_t)(b*512 + o)*SP;
            #pragma unroll
            for (int nt = 0; nt < 4; nt++) {
                int n = nBase + warp_n + nt*8 + tig*2;
                if (n < SP) {   // valid region is even-sized: pair never straddles
                    float v0 = acc[mt][nt][half*2+0] + bs[n];
                    float v1 = acc[mt][nt][half*2+1] + bs[n+1];
                    xo[n]   = fmaxf((v0 - mn)*sc + bt, 0.f);
                    xo[n+1] = fmaxf((v1 - mn)*sc + bt, 0.f);
                }
            }
        }
    }
}

// ---------------- kernel 5: 3x3 segconv (channel-split partials) ----------------
__global__ __launch_bounds__(180) void segconv_kernel(const float* __restrict__ wseg) {
    int rt = blockIdx.x, cgrp = blockIdx.y, b = blockIdx.z;
    int tid = threadIdx.x;               // 180
    int ty = tid / 30, lx = tid % 30;
    int w0 = lx * 2;
    __shared__ float sIn[8*8*64];
    __shared__ float sW[8*9*19];
    float a0[NCLS], a1[NCLS];
    #pragma unroll
    for (int o = 0; o < NCLS; o++) { a0[o] = 0.f; a1[o] = 0.f; }
    int row0 = rt * 6;
    const float* xin = g_x512 + (size_t)b * 512 * SP;
    for (int ccB = 0; ccB < 16; ccB++) {
        int c0 = cgrp*128 + ccB*8;
        for (int e = tid; e < 8*8*62; e += 180) {
            int ch = e / 496; int rem = e % 496; int r = rem / 62; int j = rem % 62;
            int gr = row0 - 1 + r, gc = j - 1;
            float v = 0.f;
            if (gr >= 0 && gr < 60 && gc >= 0 && gc < 60)
                v = xin[(size_t)(c0+ch)*SP + gr*60 + gc];
            sIn[ch*512 + r*64 + j] = v;
        }
        for (int e = tid; e < 1368; e += 180) {
            int o = e / 72; int rem = e % 72; int ch = rem / 9; int kk = rem % 9;
            sW[ch*171 + kk*19 + o] = wseg[((size_t)o*512 + c0+ch)*9 + kk];
        }
        __syncthreads();
        #pragma unroll 2
        for (int ch = 0; ch < 8; ch++) {
            #pragma unroll
            for (int ky = 0; ky < 3; ky++) {
                int base = ch*512 + (ty+ky)*64 + w0;
                float r0 = sIn[base], r1 = sIn[base+1], r2 = sIn[base+2], r3 = sIn[base+3];
                const float* wb = &sW[ch*171 + ky*57];
                #pragma unroll
                for (int o = 0; o < NCLS; o++) {
                    float w0v = wb[o], w1v = wb[19+o], w2v = wb[38+o];
                    a0[o] += r0*w0v + r1*w1v + r2*w2v;
                    a1[o] += r1*w0v + r2*w1v + r3*w2v;
                }
            }
        }
        __syncthreads();
    }
    int h = row0 + ty;
    float* pp = g_segp + (size_t)((cgrp*8 + b)*NCLS) * SP;
    #pragma unroll
    for (int o = 0; o < NCLS; o++) {
        pp[(size_t)o*SP + h*60 + w0]   = a0[o];
        pp[(size_t)o*SP + h*60 + w0+1] = a1[o];
    }
}

__global__ void segreduce_kernel(const float* __restrict__ bias) {
    int i = blockIdx.x*256 + threadIdx.x;
    if (i >= BATCH*NCLS*SP) return;
    int o = (i / SP) % NCLS;
    int b = i / (NCLS*SP);
    int hw = i % SP;
    float s = bias[o];
    #pragma unroll
    for (int c = 0; c < 4; c++) s += g_segp[(size_t)((c*8+b)*NCLS + o)*SP + hw];
    g_x60[i] = s;
}

// ---------------- kernel 6: per-pixel argmax of bilinear(x60) -> unfolded pool ----------------
__global__ void unfold_kernel() {
    int fx = blockIdx.x, fy = blockIdx.y, b = blockIdx.z;
    int t = threadIdx.x;                   // 64
    int dy = t / 8, dx = t % 8;
    int Y = fy*8 + dy, X = fx*8 + dx;
    const float r = 59.f / 479.f;
    float sy = Y * r, sx = X * r;
    int y0 = (int)sy, x0 = (int)sx;
    int y1 = min(y0+1, 59), x1 = min(x0+1, 59);
    float wy = sy - (float)y0, wx = sx - (float)x0;
    const float* xb = g_x60 + (size_t)b * NCLS * SP;
    int i00 = y0*60+x0, i01 = y0*60+x1, i10 = y1*60+x0, i11 = y1*60+x1;
    float bv = -FLT_MAX; int bi = 0;
    for (int c = 0; c < NCLS; c++) {
        const float* p = xb + (size_t)c*SP;
        float t0 = (1.f-wx)*p[i00] + wx*p[i01];
        float t1 = (1.f-wx)*p[i10] + wx*p[i11];
        float v = (1.f-wy)*t0 + wy*t1;
        if (v > bv) { bv = v; bi = c; }
    }
    __shared__ int cnt[NCLS];
    if (t < NCLS) cnt[t] = 0;
    __syncthreads();
    atomicAdd(&cnt[bi], 1);
    __syncthreads();
    if (t < NCLS) {
        int k = (fy/10)*6 + fx/10;
        int q = (fy%10)*10 + fx%10;
        g_unf[((size_t)(b*NCLS + t)*NPF + k)*100 + q] = (float)cnt[t] * (1.f/64.f);
    }
}

// ---------------- kernel 7: fused attn-matmul + fold + upsample + x*(1+corr) ----------------
__global__ __launch_bounds__(400) void final_kernel(const float* __restrict__ att,
                                                    float* __restrict__ out) {
    int b = blockIdx.z, c = blockIdx.y;
    int pbase = blockIdx.x * 64;
    int tx = threadIdx.x, ty = threadIdx.y;     // (25,16)
    int tid = ty*25 + tx;
    __shared__ __align__(16) float attT[36*65];
    __shared__ __align__(16) float unfS[3600];
    __shared__ float inv[64];
    const float* ab = att + ((size_t)(b*NCLS + c)*NPI + pbase) * 36;
    for (int e = tid; e < 64*36; e += 400) {
        int p = e / 36, k = e % 36;
        attT[k*65 + p] = ab[e];
    }
    const float* ub = g_unf + (size_t)(b*NCLS + c) * 3600;
    for (int e = tid; e < 3600; e += 400) unfS[e] = ub[e];
    __syncthreads();
    if (tid < 64) {
        int cn = 0;
        #pragma unroll 4
        for (int k = 0; k < 36; k++) cn += (attT[k*65 + tid] != 0.f);
        inv[tid] = 1.f / ((float)cn + 1e-5f);
    }
    __syncthreads();
    float acc[4][4];
    #pragma unroll
    for (int i = 0; i < 4; i++)
        #pragma unroll
        for (int j = 0; j < 4; j++) acc[i][j] = 0.f;
    int q0 = tx * 4;
    int p0 = ty * 4;
    #pragma unroll 4
    for (int k = 0; k < 36; k++) {
        float4 u = *(float4*)&unfS[k*100 + q0];
        float av0 = attT[k*65 + p0 + 0];
        float av1 = attT[k*65 + p0 + 1];
        float av2 = attT[k*65 + p0 + 2];
        float av3 = attT[k*65 + p0 + 3];
        acc[0][0] += av0*u.x; acc[0][1] += av0*u.y; acc[0][2] += av0*u.z; acc[0][3] += av0*u.w;
        acc[1][0] += av1*u.x; acc[1][1] += av1*u.y; acc[1][2] += av1*u.z; acc[1][3] += av1*u.w;
        acc[2][0] += av2*u.x; acc[2][1] += av2*u.y; acc[2][2] += av2*u.z; acc[2][3] += av2*u.w;
        acc[3][0] += av3*u.x; acc[3][1] += av3*u.y; acc[3][2] += av3*u.z; acc[3][3] += av3*u.w;
    }
    const float* xb = g_x60 + (size_t)(b*NCLS + c) * SP;
    float* ob = out + (size_t)(b*NCLS + c) * (HI*HI);
    const float r = 59.f / 479.f;
    #pragma unroll
    for (int i = 0; i < 4; i++) {
        int p = pbase + p0 + i;
        int Py = p / 48, Px = p % 48;
        float ci = inv[p0 + i];
        #pragma unroll
        for (int j = 0; j < 4; j++) {
            int q = q0 + j;
            int y = Py*10 + q/10;
            int x = Px*10 + q%10;
            float sy = y * r, sx = x * r;
            int y0 = (int)sy, x0 = (int)sx;
            int y1 = min(y0+1, 59), x1 = min(x0+1, 59);
            float wy = sy - (float)y0, wx = sx - (float)x0;
            float t0 = (1.f-wx)*xb[y0*60+x0] + wx*xb[y0*60+x1];
            float t1 = (1.f-wx)*xb[y1*60+x0] + wx*xb[y1*60+x1];
            float xv = (1.f-wy)*t0 + wy*t1;
            float corr = acc[i][j] * ci;
            ob[y*HI + x] = corr*xv + xv;
        }
    }
}

// ---------------- launcher ----------------
extern "C" void kernel_launch(void* const* d_in, const int* in_sizes, int n_in,
                              void* d_out, int out_size) {
    const float* feat   = (const float*)d_in[0];
    const float* att    = (const float*)d_in[1];
    const float* w_psp  = (const float*)d_in[2];
    const float* b_psp0 = (const float*)d_in[3];
    const float* bng    = (const float*)d_in[4];
    const float* bnb    = (const float*)d_in[5];
    const float* bnm    = (const float*)d_in[6];
    const float* bnv    = (const float*)d_in[7];
    const float* w_conv = (const float*)d_in[8];
    const float* cgam   = (const float*)d_in[9];
    const float* cbet   = (const float*)d_in[10];
    const float* cmea   = (const float*)d_in[11];
    const float* cvar   = (const float*)d_in[12];
    const float* wseg   = (const float*)d_in[13];
    const float* bseg   = (const float*)d_in[14];
    float* out = (float*)d_out;
    cudaStream_t st = 0;

    cudaFuncSetAttribute(gemm_mma_kernel, cudaFuncAttributeMaxDynamicSharedMemorySize,
                         G_SMEM_TOTAL);

    pool_kernel<<<BATCH*CIN, 360, 0, st>>>(feat);
    psp_kernel<<<BATCH*50, 512, 0, st>>>(w_psp, b_psp0, bng, bnb, bnm, bnv, w_conv);
    bsum_kernel<<<dim3(15, BATCH*CIN), 240, 0, st>>>();
    gemm_mma_kernel<<<dim3(29, 4, BATCH), 256, G_SMEM_TOTAL, st>>>(w_conv, feat, cgam, cbet, cmea, cvar);
    segconv_kernel<<<dim3(10, 4, BATCH), 180, 0, st>>>(wseg);
    segreduce_kernel<<<(BATCH*NCLS*SP + 255)/256, 256, 0, st>>>(bseg);
    unfold_kernel<<<dim3(60, 60, BATCH), 64, 0, st>>>();
    final_kernel<<<dim3(36, NCLS, BATCH), dim3(25, 16), 0, st>>>(att, out);

    long attsz = (long)in_sizes[1];
    if ((long)out_size >= XSIZE + attsz) {
        cudaMemcpyAsync(out + XSIZE, att, (size_t)attsz * sizeof(float),
                        cudaMemcpyDeviceToDevice, st);
    }
}